// round 15
// baseline (speedup 1.0000x reference)
#include <cuda_runtime.h>
#include <cstdint>

// Encoder: out[r,0] = x[r]; out[r,1+i] = square(2*pi * x[r] * 2^i), i = 0..14
//
// Exact integer decision: with t = fl32(2pi*x) = M*2^(e-150) and
// C = fl32(2pi) = Mc*2^-21 (Mc = 13176795), sign for freq i is bit (14-i) of
//   B = floor((t/C) * 2^15) = floor(M * 2^(e-114) / Mc)
// via Granlund-Montgomery: MAGIC = ceil(2^63/Mc); B = (M*MAGIC) >> (177-e)
// for e in [114,129]; else 0.  Bit-exact vs reference (rel_err == 0).
//
// R15 = R7 inner loop (confirmed best, 39.4-40.9us noise band, 7.2 TB/s
// effective) wrapped in a PERSISTENT grid-stride outer loop: grid = 148 SMs
// x 8 CTAs, each warp stays resident and processes ~14 chunks of 32 rows.
// Removes ~15k mid-kernel CTA launches / ~14 wave transitions whose store-
// pipeline drain is the last untested overhead source. All instruction-mix
// and cache-policy levers were falsified in R8/R9/R11/R13.

namespace {
constexpr float              CF    = 6.28318530717958647692f;  // fl32(2*pi) = Mc*2^-21
constexpr unsigned           MC    = 13176795u;
constexpr unsigned long long MAGIC = (0x8000000000000000ULL + (MC - 1)) / MC;
constexpr unsigned NUM_BLOCKS   = 148u * 8u;   // persistent: one wave fills the chip
constexpr unsigned THREADS      = 256u;
}

__global__ void __launch_bounds__(THREADS)
Encoder_22668837388855_kernel(const float* __restrict__ x,
                              float4* __restrict__ out4,
                              unsigned n) {
    unsigned lane     = threadIdx.x & 31u;
    unsigned warpGid  = (blockIdx.x * THREADS + threadIdx.x) >> 5;
    unsigned warpStep = (NUM_BLOCKS * THREADS) >> 5;     // total resident warps

    unsigned srBase = lane >> 2;
    unsigned w      = lane & 3u;
    unsigned sh     = 16u + (w << 2);           // word's first sign slot -> bit 31

    for (unsigned rowBase = warpGid << 5; rowBase < n; rowBase += warpStep << 5) {
        float xv = __ldg(&x[rowBase + lane]);   // coalesced 128B
        float t  = __fmul_rn(CF, xv);           // fl(2pi * x)

        unsigned tb = __float_as_uint(t);
        unsigned e  = tb >> 23;
        unsigned M  = (tb & 0x7FFFFFu) | 0x800000u;
        unsigned long long P = (unsigned long long)M * MAGIC;
        unsigned B = (e >= 114u) ? (unsigned)(P >> (177u - e)) : 0u;  // exact

        size_t outBase = (size_t)rowBase * 4 + lane;

#pragma unroll
        for (unsigned j = 0; j < 4; j++) {
            unsigned sr = srBase + (j << 3);
            unsigned Bs = __shfl_sync(0xFFFFFFFFu, B,  sr);
            float    xs = __shfl_sync(0xFFFFFFFFu, xv, sr);

            unsigned bs = Bs << sh;
            float4 o;
            o.x = __uint_as_float((bs & 0x80000000u) | 0x3F800000u); bs += bs;
            o.y = __uint_as_float((bs & 0x80000000u) | 0x3F800000u); bs += bs;
            o.z = __uint_as_float((bs & 0x80000000u) | 0x3F800000u); bs += bs;
            o.w = __uint_as_float((bs & 0x80000000u) | 0x3F800000u);
            if (w == 0) o.x = xs;               // col 0 of each row is raw x

            __stcs(&out4[outBase + (size_t)(j << 5)], o);
        }
    }
}

extern "C" void kernel_launch(void* const* d_in, const int* in_sizes, int n_in,
                              void* d_out, int out_size) {
    const float* x = (const float*)d_in[0];
    float4* out = (float4*)d_out;
    unsigned n = (unsigned)in_sizes[0];
    Encoder_22668837388855_kernel<<<NUM_BLOCKS, THREADS>>>(x, out, n);
}

// round 16
// speedup vs baseline: 1.1371x; 1.1371x over previous
#include <cuda_runtime.h>
#include <cstdint>

// Encoder: out[r,0] = x[r]; out[r,1+i] = square(2*pi * x[r] * 2^i), i = 0..14
//
// Exact integer decision: with t = fl32(2pi*x) = M*2^(e-150) and
// C = fl32(2pi) = Mc*2^-21 (Mc = 13176795), sign for freq i is bit (14-i) of
//   B = floor((t/C) * 2^15) = floor(M * 2^(e-114) / Mc)
// computed exactly via Granlund-Montgomery invariant division:
//   MAGIC = ceil(2^63/Mc);  B = (M*MAGIC) >> (177-e) for e in [114,129]; else 0.
// Bit-exact vs the reference (rel_err == 0).
//
// TERMINAL FORM (= R7; best: 39.4us twice, noise band 39.4-40.9us,
// 7.2 TB/s effective ~= 90% of HBM3e spec — the write-stream roofline for
// this 16:1 write:read kernel). Falsified alternatives (all >= 42.8us
// profiled, memory counters unchanged or worse):
//   R5  1 row/thread, 64B-lane-stride stores  (4x L1 wavefront amplification)
//   R8  no-shuffle recompute                   (issue/ALU not the binder)
//   R9  smem + cp.async.bulk store             (LSU issue cost not the binder)
//   R11 st.global.v8.f32 256-bit stores        (store instr count not the binder)
//   R13 st.global.wt                           (L2 write-policy regression)
//   R15 persistent grid-stride                 (loop-carried dep kills store MLP)
//
// Structure: each warp owns 32 rows. Lane L computes row rowBase+L's 15-bit
// decision word B ONCE (coalesced 128B LDG of x), then the warp's 128 output
// float4 words are written as 4 perfectly coalesced STG.128s (4 independent
// stores in flight), each lane pulling its source row's (B, x) via shuffle.

namespace {
constexpr float              CF    = 6.28318530717958647692f;  // fl32(2*pi) = Mc*2^-21
constexpr unsigned           MC    = 13176795u;
constexpr unsigned long long MAGIC = (0x8000000000000000ULL + (MC - 1)) / MC;
}

__global__ void __launch_bounds__(256)
Encoder_22668837388855_kernel(const float* __restrict__ x,
                              float4* __restrict__ out4,
                              unsigned n) {
    unsigned lane    = threadIdx.x & 31u;
    unsigned warpGid = (blockIdx.x * blockDim.x + threadIdx.x) >> 5;
    unsigned rowBase = warpGid << 5;            // 32 rows per warp
    if (rowBase >= n) return;                   // n % 32 == 0: whole-warp guard

    float xv = __ldg(&x[rowBase + lane]);       // coalesced 128B
    float t  = __fmul_rn(CF, xv);               // fl(2pi * x)

    unsigned tb = __float_as_uint(t);
    unsigned e  = tb >> 23;
    unsigned M  = (tb & 0x7FFFFFu) | 0x800000u;
    unsigned long long P = (unsigned long long)M * MAGIC;
    unsigned B = (e >= 114u) ? (unsigned)(P >> (177u - e)) : 0u;  // exact floor(u*2^15)

    // Emit 128 words (32 rows x 4 float4) as 4 coalesced STG.128s.
    // Store j, lane L writes word rowBase*4 + j*32 + L == row (j*8 + L/4),
    // word w = L & 3 of that row.
    unsigned srBase = lane >> 2;
    unsigned w      = lane & 3u;
    unsigned sh     = 16u + (w << 2);           // word's first sign slot -> bit 31

    size_t outBase = (size_t)rowBase * 4 + lane;

#pragma unroll
    for (unsigned j = 0; j < 4; j++) {
        unsigned sr = srBase + (j << 3);
        unsigned Bs = __shfl_sync(0xFFFFFFFFu, B,  sr);
        float    xs = __shfl_sync(0xFFFFFFFFu, xv, sr);

        unsigned bs = Bs << sh;
        float4 o;
        o.x = __uint_as_float((bs & 0x80000000u) | 0x3F800000u); bs += bs;
        o.y = __uint_as_float((bs & 0x80000000u) | 0x3F800000u); bs += bs;
        o.z = __uint_as_float((bs & 0x80000000u) | 0x3F800000u); bs += bs;
        o.w = __uint_as_float((bs & 0x80000000u) | 0x3F800000u);
        if (w == 0) o.x = xs;                   // col 0 of each row is raw x

        __stcs(&out4[outBase + (size_t)(j << 5)], o);
    }
}

extern "C" void kernel_launch(void* const* d_in, const int* in_sizes, int n_in,
                              void* d_out, int out_size) {
    const float* x = (const float*)d_in[0];
    float4* out = (float4*)d_out;
    unsigned n = (unsigned)in_sizes[0];
    unsigned warps  = (n + 31u) / 32u;
    unsigned total  = warps * 32u;
    int threads = 256;
    unsigned blocks = (total + threads - 1) / threads;
    Encoder_22668837388855_kernel<<<blocks, threads>>>(x, out, n);
}